// round 10
// baseline (speedup 1.0000x reference)
#include <cuda_runtime.h>
#include <cstdint>
#include <cstddef>

typedef unsigned long long ull;

#define S_LEN 512
#define B_SZ  256
#define D_SZ  128
#define R_SZ  2048

__device__ float  g_hist[(size_t)S_LEN * B_SZ * R_SZ];
__device__ double g_pc_part[8];
__device__ double g_mse_part[128];

__device__ __forceinline__ ull pk2(float lo, float hi) {
    ull r; asm("mov.b64 %0, {%1,%2};" : "=l"(r) : "f"(lo), "f"(hi)); return r;
}
__device__ __forceinline__ void upk2(float& lo, float& hi, ull v) {
    asm("mov.b64 {%0,%1}, %2;" : "=f"(lo), "=f"(hi) : "l"(v));
}
__device__ __forceinline__ ull fma2(ull a, ull b, ull c) {
    ull d; asm("fma.rn.f32x2 %0, %1, %2, %3;" : "=l"(d) : "l"(a), "l"(b), "l"(c)); return d;
}
__device__ __forceinline__ float clip5(float v) { return fminf(fmaxf(v, -5.f), 5.f); }

// XLA:GPU-contracted oscillator step (matched recipe — DO NOT CHANGE)
__device__ __forceinline__ float osc_upd(float f, float& x, float& y,
                                         float a, float g2, float w2) {
    float gy = __fmul_rn(g2, y);
    float ac = fmaf(-w2, x, fmaf(a, f, -gy));
    float xn = clip5(fmaf(0.5f, y, x));
    float yn = clip5(fmaf(0.5f, ac, y));
    x = xn; y = yn;
    return xn;
}

// ============ Phase A: persistent recurrence ============
// Grid (16 col-blocks, 8 row-blocks), 512 threads (16 warps, 4/SMSP).
// Thread tile: 2 rows x 4 cols. smem: wt[128][128] + xs[128 d][32 rows].
__global__ void __launch_bounds__(512, 1) phaseA_kernel(
    const float* __restrict__ inputs,
    const float* __restrict__ om_in, const float* __restrict__ ga_in, const float* __restrict__ al_in,
    const float* __restrict__ Wp,    const float* __restrict__ bp,
    const float* __restrict__ om_r,  const float* __restrict__ ga_r,  const float* __restrict__ al_r,
    const float* __restrict__ om_o,  const float* __restrict__ ga_o,  const float* __restrict__ al_o)
{
    const int cb  = blockIdx.x;   // 0..15 reservoir col block
    const int rb  = blockIdx.y;   // 0..7  batch row block
    const int tid = threadIdx.x;

    extern __shared__ float smem[];
    float* wt = smem;                 // [128 d][128 c]
    float* xs = smem + 128 * 128;     // [128 d][32 rows]

    __shared__ float  pa[128], pg[128], pw[128];
    __shared__ double redd[512];

    for (int i = tid; i < 4096; i += 512) {
        int c = i >> 5, d0 = (i & 31) << 2;
        float4 v = *(const float4*)(Wp + ((size_t)(cb * 128 + c)) * D_SZ + d0);
        wt[(d0+0)*128 + c] = v.x; wt[(d0+1)*128 + c] = v.y;
        wt[(d0+2)*128 + c] = v.z; wt[(d0+3)*128 + c] = v.w;
    }
    if (tid < 128) {
        pa[tid] = al_in[tid];
        pg[tid] = __fmul_rn(2.f, fabsf(ga_in[tid]));
        float o = fabsf(om_in[tid]); pw[tid] = __fmul_rn(o, o);
    }

    // input-oscillator mapping: 32 rows x 16 d-chunks of 8
    const int irow = tid & 31;
    const int dch  = (tid >> 5) << 3;     // warp*8
    const int gb_i = rb * 32 + irow;

    // GEMM mapping: 2 rows x 4 cols per thread
    const int lane = tid & 31, warp = tid >> 5;
    const int r0 = (lane & 15) << 1;               // row pair base (0..30)
    const int c0 = warp * 8 + ((lane >> 4) << 2);  // col base (0..124)

    float par[4], pgr[4], pwr[4], pao[4], pgo[4], pwo[4], bpv[4];
    {
        int rbase = cb * 128 + c0;
        #pragma unroll
        for (int j = 0; j < 4; ++j) {
            par[j] = al_r[rbase+j];
            pgr[j] = __fmul_rn(2.f, fabsf(ga_r[rbase+j]));
            float o = fabsf(om_r[rbase+j]); pwr[j] = __fmul_rn(o, o);
            pao[j] = al_o[rbase+j];
            pgo[j] = __fmul_rn(2.f, fabsf(ga_o[rbase+j]));
            float q = fabsf(om_o[rbase+j]); pwo[j] = __fmul_rn(q, q);
            bpv[j] = bp[rbase+j];
        }
    }

    float x_in[8], y_in[8], xr[8], yr[8], xo[8], yo[8];
    #pragma unroll
    for (int k = 0; k < 8; ++k) { x_in[k]=0.f; y_in[k]=0.f; xr[k]=0.f; yr[k]=0.f; xo[k]=0.f; yo[k]=0.f; }

    double lin = 0.0, lmse = 0.0;

    float inpv[8];
    {
        const float* p = inputs + (size_t)gb_i * (S_LEN * D_SZ) + dch;
        float4 v0 = *(const float4*)(p);
        float4 v1 = *(const float4*)(p + 4);
        inpv[0]=v0.x; inpv[1]=v0.y; inpv[2]=v0.z; inpv[3]=v0.w;
        inpv[4]=v1.x; inpv[5]=v1.y; inpv[6]=v1.z; inpv[7]=v1.w;
    }
    __syncthreads();   // staging complete before any use

    for (int t = 0; t < S_LEN; ++t) {
        if (t > 0) {
            float ls = 0.f;
            #pragma unroll
            for (int k = 0; k < 8; ++k) { float df = x_in[k]-inpv[k]; ls = fmaf(df, df, ls); }
            lin += (double)ls;
        }
        #pragma unroll
        for (int k = 0; k < 8; ++k) {
            int d = dch + k;
            osc_upd(inpv[k], x_in[k], y_in[k], pa[d], pg[d], pw[d]);
        }
        __syncthreads();   // prev step's GEMM readers done with xs
        #pragma unroll
        for (int k = 0; k < 8; ++k)
            xs[(dch + k) * 32 + irow] = x_in[k];
        __syncthreads();

        {   // prefetch next input slice under the GEMM
            int tn = (t < S_LEN-1) ? t+1 : t;
            const float* p = inputs + (size_t)gb_i * (S_LEN*D_SZ) + (size_t)tn * D_SZ + dch;
            float4 v0 = *(const float4*)(p);
            float4 v1 = *(const float4*)(p + 4);
            inpv[0]=v0.x; inpv[1]=v0.y; inpv[2]=v0.z; inpv[3]=v0.w;
            inpv[4]=v1.x; inpv[5]=v1.y; inpv[6]=v1.z; inpv[7]=v1.w;
        }

        // GEMM1 tile: proj = x_in @ Wp^T
        // acc[j] packs rows (r0, r0+1) for col c0+j.
        // Per element: acc=0, ascending-d fma chain — identical math.
        ull acc[4];
        #pragma unroll
        for (int j = 0; j < 4; ++j) acc[j] = 0ull;

        #pragma unroll 8
        for (int d = 0; d < 128; d += 2) {
            float2 xa = *(const float2*)(xs + d*32 + r0);
            float2 xb = *(const float2*)(xs + (d+1)*32 + r0);
            float4 wa = *(const float4*)(wt + d*128 + c0);
            float4 wb = *(const float4*)(wt + (d+1)*128 + c0);
            ull xap = pk2(xa.x, xa.y);
            ull xbp = pk2(xb.x, xb.y);
            float wav[4] = {wa.x, wa.y, wa.z, wa.w};
            float wbv[4] = {wb.x, wb.y, wb.z, wb.w};
            #pragma unroll
            for (int j = 0; j < 4; ++j) {
                acc[j] = fma2(xap, pk2(wav[j], wav[j]), acc[j]);
                acc[j] = fma2(xbp, pk2(wbv[j], wbv[j]), acc[j]);
            }
        }

        // unpack: element (i row, j col), i<2
        float fv[2][4];
        #pragma unroll
        for (int j = 0; j < 4; ++j) {
            float lo, hi; upk2(lo, hi, acc[j]);
            fv[0][j] = lo; fv[1][j] = hi;
        }

        float ls2 = 0.f;
        #pragma unroll
        for (int i = 0; i < 2; ++i) {
            #pragma unroll
            for (int j = 0; j < 4; ++j) {
                int k = i*4 + j;
                float f = __fadd_rn(fv[i][j], bpv[j]);   // bias after dot (matched)
                float xrn = osc_upd(f,   xr[k], yr[k], par[j], pgr[j], pwr[j]);
                float xon = osc_upd(xrn, xo[k], yo[k], pao[j], pgo[j], pwo[j]);
                float df = xon - xrn;
                ls2 = fmaf(df, df, ls2);
            }
        }
        lmse += (double)ls2;

        size_t hb = ((size_t)t * B_SZ + rb*32 + r0) * R_SZ + cb*128 + c0;
        *(float4*)(g_hist + hb)            = make_float4(xo[0], xo[1], xo[2], xo[3]);
        *(float4*)(g_hist + hb + R_SZ)     = make_float4(xo[4], xo[5], xo[6], xo[7]);
    }

    __syncthreads();
    redd[tid] = lin; __syncthreads();
    for (int s = 256; s > 0; s >>= 1) { if (tid < s) redd[tid] += redd[tid+s]; __syncthreads(); }
    if (tid == 0 && cb == 0) g_pc_part[rb] = redd[0];
    __syncthreads();
    redd[tid] = lmse; __syncthreads();
    for (int s = 256; s > 0; s >>= 1) { if (tid < s) redd[tid] += redd[tid+s]; __syncthreads(); }
    if (tid == 0) g_mse_part[rb*16 + cb] = redd[0];
}

// ============ Phase B: preds = hist @ W_read^T + b_read ============
// CTA tile: 128 rows x 64 cols. Grid (1024, 2), 256 threads.
// Thread: 8 rows (4 row-pairs spaced 32) x 4 cols. k-major smem staging.
#define AS_PITCH 130
#define WS_PITCH 68
__global__ void __launch_bounds__(256, 2) gemm2_kernel(
    const float* __restrict__ Wr, const float* __restrict__ brd, float* __restrict__ out)
{
    __shared__ __align__(16) float ws[32 * WS_PITCH];    // ws[k][c], c<64
    __shared__ __align__(16) float as2[32 * AS_PITCH];   // as2[k][r], r<128

    const int tid = threadIdx.x;
    const int lane = tid & 31, warp = tid >> 5;
    const int rg = lane & 15, cg = lane >> 4;
    const int r0 = rg * 2;                   // rows r0 + rp*32 + {0,1}
    const int c0 = warp * 8 + cg * 4;        // local col base (0..60 within 64)
    const int C0 = blockIdx.y * 64;
    const size_t mBase = (size_t)blockIdx.x * 128;

    ull acc[4][4];
    #pragma unroll
    for (int rp = 0; rp < 4; ++rp)
        #pragma unroll
        for (int j = 0; j < 4; ++j) acc[rp][j] = 0ull;

    for (int kc = 0; kc < R_SZ; kc += 32) {
        __syncthreads();
        // stage W chunk k-major: ws[k][c] = Wr[(C0+c)*R + kc+k]
        for (int i = tid; i < 512; i += 256) {
            int c = i >> 3, kk = (i & 7) << 2;
            float4 v = *(const float4*)(Wr + (size_t)(C0 + c) * R_SZ + kc + kk);
            ws[(kk+0)*WS_PITCH + c] = v.x; ws[(kk+1)*WS_PITCH + c] = v.y;
            ws[(kk+2)*WS_PITCH + c] = v.z; ws[(kk+3)*WS_PITCH + c] = v.w;
        }
        // stage hist chunk k-major: as2[k][r] = hist[mBase+r][kc+k]
        for (int i = tid; i < 1024; i += 256) {
            int r = i >> 3, kk = (i & 7) << 2;
            float4 v = *(const float4*)(g_hist + (mBase + r) * R_SZ + kc + kk);
            as2[(kk+0)*AS_PITCH + r] = v.x; as2[(kk+1)*AS_PITCH + r] = v.y;
            as2[(kk+2)*AS_PITCH + r] = v.z; as2[(kk+3)*AS_PITCH + r] = v.w;
        }
        __syncthreads();

        #pragma unroll 8
        for (int k = 0; k < 32; ++k) {
            float4 wv = *(const float4*)(ws + k*WS_PITCH + c0);
            ull wd0 = pk2(wv.x, wv.x), wd1 = pk2(wv.y, wv.y);
            ull wd2 = pk2(wv.z, wv.z), wd3 = pk2(wv.w, wv.w);
            #pragma unroll
            for (int rp = 0; rp < 4; ++rp) {
                float2 xv = *(const float2*)(as2 + k*AS_PITCH + rp*32 + r0);
                ull xp = pk2(xv.x, xv.y);
                acc[rp][0] = fma2(xp, wd0, acc[rp][0]);
                acc[rp][1] = fma2(xp, wd1, acc[rp][1]);
                acc[rp][2] = fma2(xp, wd2, acc[rp][2]);
                acc[rp][3] = fma2(xp, wd3, acc[rp][3]);
            }
        }
    }

    float bv[4];
    #pragma unroll
    for (int j = 0; j < 4; ++j) bv[j] = brd[C0 + c0 + j];

    #pragma unroll
    for (int rp = 0; rp < 4; ++rp) {
        float lo[4], hi[4];
        #pragma unroll
        for (int j = 0; j < 4; ++j) upk2(lo[j], hi[j], acc[rp][j]);
        #pragma unroll
        for (int h = 0; h < 2; ++h) {
            size_t m = mBase + rp*32 + r0 + h;
            int b = (int)(m & 255), t = (int)(m >> 8);
            float* o = out + (size_t)b * (S_LEN * D_SZ) + (size_t)t * D_SZ + C0 + c0;
            float* src = h ? hi : lo;
            *(float4*)(o) = make_float4(__fadd_rn(src[0], bv[0]), __fadd_rn(src[1], bv[1]),
                                        __fadd_rn(src[2], bv[2]), __fadd_rn(src[3], bv[3]));
        }
    }
}

// ============ Final loss reduce ============
__global__ void reduce_kernel(float* __restrict__ out, int out_size)
{
    if (threadIdx.x != 0 || blockIdx.x != 0) return;
    double a = 0.0, b = 0.0;
    for (int i = 0; i < 8; ++i)   a += g_pc_part[i];
    for (int i = 0; i < 128; ++i) b += g_mse_part[i];
    a /= (double)(B_SZ * D_SZ);
    b /= (double)(B_SZ * R_SZ);
    size_t base = (size_t)B_SZ * S_LEN * D_SZ;
    if ((size_t)out_size >= base + 2) {
        out[base]     = (float)a;
        out[base + 1] = (float)b;
    }
}

extern "C" void kernel_launch(void* const* d_in, const int* in_sizes, int n_in,
                              void* d_out, int out_size)
{
    const float* inputs = (const float*)d_in[0];
    const float* om_in  = (const float*)d_in[1];
    const float* ga_in  = (const float*)d_in[2];
    const float* al_in  = (const float*)d_in[3];
    const float* Wp     = (const float*)d_in[4];
    const float* bp     = (const float*)d_in[5];
    const float* om_r   = (const float*)d_in[6];
    const float* ga_r   = (const float*)d_in[7];
    const float* al_r   = (const float*)d_in[8];
    const float* om_o   = (const float*)d_in[9];
    const float* ga_o   = (const float*)d_in[10];
    const float* al_o   = (const float*)d_in[11];
    const float* Wr     = (const float*)d_in[12];
    const float* brd    = (const float*)d_in[13];
    float* out = (float*)d_out;

    cudaFuncSetAttribute(phaseA_kernel,
        cudaFuncAttributeMaxDynamicSharedMemorySize, 81920);

    dim3 gA(16, 8);
    phaseA_kernel<<<gA, 512, 81920>>>(inputs, om_in, ga_in, al_in, Wp, bp,
                                      om_r, ga_r, al_r, om_o, ga_o, al_o);
    dim3 gB(1024, 2);
    gemm2_kernel<<<gB, 256>>>(Wr, brd, out);
    reduce_kernel<<<1, 1>>>(out, out_size);
}

// round 12
// speedup vs baseline: 1.1602x; 1.1602x over previous
#include <cuda_runtime.h>
#include <cstdint>
#include <cstddef>

typedef unsigned long long ull;

#define S_LEN 512
#define B_SZ  256
#define D_SZ  128
#define R_SZ  2048

__device__ float  g_hist[(size_t)S_LEN * B_SZ * R_SZ];
__device__ double g_pc_part[8];
__device__ double g_mse_part[128];

__device__ __forceinline__ ull pk2(float lo, float hi) {
    ull r; asm("mov.b64 %0, {%1,%2};" : "=l"(r) : "f"(lo), "f"(hi)); return r;
}
__device__ __forceinline__ void upk2(float& lo, float& hi, ull v) {
    asm("mov.b64 {%0,%1}, %2;" : "=f"(lo), "=f"(hi) : "l"(v));
}
__device__ __forceinline__ ull fma2(ull a, ull b, ull c) {
    ull d; asm("fma.rn.f32x2 %0, %1, %2, %3;" : "=l"(d) : "l"(a), "l"(b), "l"(c)); return d;
}
__device__ __forceinline__ float clip5(float v) { return fminf(fmaxf(v, -5.f), 5.f); }

// XLA:GPU-contracted oscillator step (matched recipe — DO NOT CHANGE)
__device__ __forceinline__ float osc_upd(float f, float& x, float& y,
                                         float a, float g2, float w2) {
    float gy = __fmul_rn(g2, y);
    float ac = fmaf(-w2, x, fmaf(a, f, -gy));
    float xn = clip5(fmaf(0.5f, y, x));
    float yn = clip5(fmaf(0.5f, ac, y));
    x = xn; y = yn;
    return xn;
}

// ============ Phase A: persistent recurrence ============
// Grid (16 col-blocks, 8 row-blocks), 256 threads. Thread tile 4r x 4c.
// smem: wt[128][128] (64KB) + double-buffered xs[2][128 d][32 rows] (2x16KB).
// ONE barrier per step (write buf t&1, read buf t&1; next step writes the other).
__global__ void __launch_bounds__(256, 1) phaseA_kernel(
    const float* __restrict__ inputs,
    const float* __restrict__ om_in, const float* __restrict__ ga_in, const float* __restrict__ al_in,
    const float* __restrict__ Wp,    const float* __restrict__ bp,
    const float* __restrict__ om_r,  const float* __restrict__ ga_r,  const float* __restrict__ al_r,
    const float* __restrict__ om_o,  const float* __restrict__ ga_o,  const float* __restrict__ al_o)
{
    const int cb  = blockIdx.x;   // 0..15 reservoir col block
    const int rb  = blockIdx.y;   // 0..7  batch row block
    const int tid = threadIdx.x;

    extern __shared__ float smem[];
    float* wt  = smem;                    // [128 d][128 c]
    float* xs0 = smem + 128 * 128;        // [128 d][32 rows]
    float* xs1 = xs0 + 128 * 32;          // [128 d][32 rows]

    __shared__ float  pa[128], pg[128], pw[128];
    __shared__ double redd[256];

    // stage W_proj tile transposed: wt[d][c] = Wp[cb*128+c][d]
    for (int i = tid; i < 4096; i += 256) {
        int c = i >> 5, d0 = (i & 31) << 2;
        float4 v = *(const float4*)(Wp + ((size_t)(cb * 128 + c)) * D_SZ + d0);
        wt[(d0+0)*128 + c] = v.x; wt[(d0+1)*128 + c] = v.y;
        wt[(d0+2)*128 + c] = v.z; wt[(d0+3)*128 + c] = v.w;
    }
    if (tid < 128) {
        pa[tid] = al_in[tid];
        pg[tid] = __fmul_rn(2.f, fabsf(ga_in[tid]));
        float o = fabsf(om_in[tid]); pw[tid] = __fmul_rn(o, o);
    }

    // input-oscillator mapping: row = lane, 16 consecutive d per warp
    const int irow = tid & 31;            // 0..31
    const int dch  = (tid >> 5) << 4;     // warp*16
    const int gb_i = rb * 32 + irow;

    // GEMM mapping: 4 rows x 4 cols per thread (row-pair f32x2 packing)
    const int lane = tid & 31, warp = tid >> 5;
    const int r0 = (lane & 7) << 2;
    const int c0 = warp * 16 + ((lane >> 3) << 2);

    float par[4], pgr[4], pwr[4], pao[4], pgo[4], pwo[4], bpv[4];
    {
        int rbase = cb * 128 + c0;
        #pragma unroll
        for (int j = 0; j < 4; ++j) {
            par[j] = al_r[rbase+j];
            pgr[j] = __fmul_rn(2.f, fabsf(ga_r[rbase+j]));
            float o = fabsf(om_r[rbase+j]); pwr[j] = __fmul_rn(o, o);
            pao[j] = al_o[rbase+j];
            pgo[j] = __fmul_rn(2.f, fabsf(ga_o[rbase+j]));
            float q = fabsf(om_o[rbase+j]); pwo[j] = __fmul_rn(q, q);
            bpv[j] = bp[rbase+j];
        }
    }

    float x_in[16], y_in[16], xr[16], yr[16], xo[16], yo[16];
    #pragma unroll
    for (int k = 0; k < 16; ++k) { x_in[k]=0.f; y_in[k]=0.f; xr[k]=0.f; yr[k]=0.f; xo[k]=0.f; yo[k]=0.f; }

    double lin = 0.0, lmse = 0.0;

    float inpv[16];
    {
        const float* p = inputs + (size_t)gb_i * (S_LEN * D_SZ) + dch;
        #pragma unroll
        for (int q = 0; q < 4; ++q) {
            float4 v = *(const float4*)(p + q*4);
            inpv[q*4]=v.x; inpv[q*4+1]=v.y; inpv[q*4+2]=v.z; inpv[q*4+3]=v.w;
        }
    }
    __syncthreads();   // staging complete before any use

    for (int t = 0; t < S_LEN; ++t) {
        float* xs = (t & 1) ? xs1 : xs0;

        if (t > 0) {
            float ls = 0.f;
            #pragma unroll
            for (int k = 0; k < 16; ++k) { float df = x_in[k]-inpv[k]; ls = fmaf(df, df, ls); }
            lin += (double)ls;
        }
        #pragma unroll
        for (int k = 0; k < 16; ++k) {
            int d = dch + k;
            osc_upd(inpv[k], x_in[k], y_in[k], pa[d], pg[d], pw[d]);
        }
        // write this step's x tile into buffer t&1 (other buffer may still be read
        // by trailing warps of step t-1 — no conflict)
        #pragma unroll
        for (int k = 0; k < 16; ++k)
            xs[(dch + k) * 32 + irow] = x_in[k];
        __syncthreads();   // the ONLY barrier per step

        {   // prefetch next input slice under the GEMM
            int tn = (t < S_LEN-1) ? t+1 : t;
            const float* p = inputs + (size_t)gb_i * (S_LEN*D_SZ) + (size_t)tn * D_SZ + dch;
            #pragma unroll
            for (int q = 0; q < 4; ++q) {
                float4 v = *(const float4*)(p + q*4);
                inpv[q*4]=v.x; inpv[q*4+1]=v.y; inpv[q*4+2]=v.z; inpv[q*4+3]=v.w;
            }
        }

        // GEMM1 tile: proj = x_in @ Wp^T
        // acc[rp][j] packs rows (r0+2rp, r0+2rp+1) for col c0+j.
        // Per element: acc=0, ascending-d fma chain — identical math.
        ull acc[2][4];
        #pragma unroll
        for (int j = 0; j < 4; ++j) { acc[0][j] = 0ull; acc[1][j] = 0ull; }

        #pragma unroll 8
        for (int d = 0; d < 128; d += 2) {
            float4 xa = *(const float4*)(xs + d*32 + r0);        // rows r0..r0+3 @ d
            float4 xb = *(const float4*)(xs + (d+1)*32 + r0);    // rows r0..r0+3 @ d+1
            float4 wa = *(const float4*)(wt + d*128 + c0);       // cols c0..c0+3 @ d
            float4 wb = *(const float4*)(wt + (d+1)*128 + c0);
            ull xa0 = pk2(xa.x, xa.y), xa1 = pk2(xa.z, xa.w);
            ull xb0 = pk2(xb.x, xb.y), xb1 = pk2(xb.z, xb.w);
            float wav[4] = {wa.x, wa.y, wa.z, wa.w};
            float wbv[4] = {wb.x, wb.y, wb.z, wb.w};
            #pragma unroll
            for (int j = 0; j < 4; ++j) {
                ull wda = pk2(wav[j], wav[j]);
                ull wdb = pk2(wbv[j], wbv[j]);
                acc[0][j] = fma2(xa0, wda, acc[0][j]);
                acc[1][j] = fma2(xa1, wda, acc[1][j]);
                acc[0][j] = fma2(xb0, wdb, acc[0][j]);
                acc[1][j] = fma2(xb1, wdb, acc[1][j]);
            }
        }

        // unpack: element (i row, j col), i = 2*rp + half
        float fv[4][4];
        #pragma unroll
        for (int rp = 0; rp < 2; ++rp)
            #pragma unroll
            for (int j = 0; j < 4; ++j) {
                float lo, hi; upk2(lo, hi, acc[rp][j]);
                fv[2*rp][j] = lo; fv[2*rp+1][j] = hi;
            }

        float ls2 = 0.f;
        #pragma unroll
        for (int i = 0; i < 4; ++i) {
            #pragma unroll
            for (int j = 0; j < 4; ++j) {
                int k = i*4 + j;
                float f = __fadd_rn(fv[i][j], bpv[j]);   // bias after dot (matched)
                float xrn = osc_upd(f,   xr[k], yr[k], par[j], pgr[j], pwr[j]);
                float xon = osc_upd(xrn, xo[k], yo[k], pao[j], pgo[j], pwo[j]);
                float df = xon - xrn;
                ls2 = fmaf(df, df, ls2);
            }
        }
        lmse += (double)ls2;

        size_t hb = ((size_t)t * B_SZ + rb*32 + r0) * R_SZ + cb*128 + c0;
        #pragma unroll
        for (int i = 0; i < 4; ++i)
            *(float4*)(g_hist + hb + (size_t)i * R_SZ) =
                make_float4(xo[i*4], xo[i*4+1], xo[i*4+2], xo[i*4+3]);
    }

    __syncthreads();
    redd[tid] = lin; __syncthreads();
    for (int s = 128; s > 0; s >>= 1) { if (tid < s) redd[tid] += redd[tid+s]; __syncthreads(); }
    if (tid == 0 && cb == 0) g_pc_part[rb] = redd[0];
    __syncthreads();
    redd[tid] = lmse; __syncthreads();
    for (int s = 128; s > 0; s >>= 1) { if (tid < s) redd[tid] += redd[tid+s]; __syncthreads(); }
    if (tid == 0) g_mse_part[rb*16 + cb] = redd[0];
}

// ============ Phase B: preds = hist @ W_read^T + b_read ============
// CTA tile: 128 rows x 64 cols. Grid (1024, 2), 256 threads.
// Thread: 8 rows (4 row-pairs spaced 32) x 4 cols. k-major smem staging.
#define AS_PITCH 130
#define WS_PITCH 68
__global__ void __launch_bounds__(256, 2) gemm2_kernel(
    const float* __restrict__ Wr, const float* __restrict__ brd, float* __restrict__ out)
{
    __shared__ __align__(16) float ws[32 * WS_PITCH];    // ws[k][c], c<64
    __shared__ __align__(16) float as2[32 * AS_PITCH];   // as2[k][r], r<128

    const int tid = threadIdx.x;
    const int lane = tid & 31, warp = tid >> 5;
    const int rg = lane & 15, cg = lane >> 4;
    const int r0 = rg * 2;                   // rows r0 + rp*32 + {0,1}
    const int c0 = warp * 8 + cg * 4;        // local col base (0..60 within 64)
    const int C0 = blockIdx.y * 64;
    const size_t mBase = (size_t)blockIdx.x * 128;

    ull acc[4][4];
    #pragma unroll
    for (int rp = 0; rp < 4; ++rp)
        #pragma unroll
        for (int j = 0; j < 4; ++j) acc[rp][j] = 0ull;

    for (int kc = 0; kc < R_SZ; kc += 32) {
        __syncthreads();
        // stage W chunk k-major: ws[k][c] = Wr[(C0+c)*R + kc+k]
        for (int i = tid; i < 512; i += 256) {
            int c = i >> 3, kk = (i & 7) << 2;
            float4 v = *(const float4*)(Wr + (size_t)(C0 + c) * R_SZ + kc + kk);
            ws[(kk+0)*WS_PITCH + c] = v.x; ws[(kk+1)*WS_PITCH + c] = v.y;
            ws[(kk+2)*WS_PITCH + c] = v.z; ws[(kk+3)*WS_PITCH + c] = v.w;
        }
        // stage hist chunk k-major: as2[k][r] = hist[mBase+r][kc+k]
        for (int i = tid; i < 1024; i += 256) {
            int r = i >> 3, kk = (i & 7) << 2;
            float4 v = *(const float4*)(g_hist + (mBase + r) * R_SZ + kc + kk);
            as2[(kk+0)*AS_PITCH + r] = v.x; as2[(kk+1)*AS_PITCH + r] = v.y;
            as2[(kk+2)*AS_PITCH + r] = v.z; as2[(kk+3)*AS_PITCH + r] = v.w;
        }
        __syncthreads();

        #pragma unroll 8
        for (int k = 0; k < 32; ++k) {
            float4 wv = *(const float4*)(ws + k*WS_PITCH + c0);
            ull wd0 = pk2(wv.x, wv.x), wd1 = pk2(wv.y, wv.y);
            ull wd2 = pk2(wv.z, wv.z), wd3 = pk2(wv.w, wv.w);
            #pragma unroll
            for (int rp = 0; rp < 4; ++rp) {
                float2 xv = *(const float2*)(as2 + k*AS_PITCH + rp*32 + r0);
                ull xp = pk2(xv.x, xv.y);
                acc[rp][0] = fma2(xp, wd0, acc[rp][0]);
                acc[rp][1] = fma2(xp, wd1, acc[rp][1]);
                acc[rp][2] = fma2(xp, wd2, acc[rp][2]);
                acc[rp][3] = fma2(xp, wd3, acc[rp][3]);
            }
        }
    }

    float bv[4];
    #pragma unroll
    for (int j = 0; j < 4; ++j) bv[j] = brd[C0 + c0 + j];

    #pragma unroll
    for (int rp = 0; rp < 4; ++rp) {
        float lo[4], hi[4];
        #pragma unroll
        for (int j = 0; j < 4; ++j) upk2(lo[j], hi[j], acc[rp][j]);
        #pragma unroll
        for (int h = 0; h < 2; ++h) {
            size_t m = mBase + rp*32 + r0 + h;
            int b = (int)(m & 255), t = (int)(m >> 8);
            float* o = out + (size_t)b * (S_LEN * D_SZ) + (size_t)t * D_SZ + C0 + c0;
            float* src = h ? hi : lo;
            *(float4*)(o) = make_float4(__fadd_rn(src[0], bv[0]), __fadd_rn(src[1], bv[1]),
                                        __fadd_rn(src[2], bv[2]), __fadd_rn(src[3], bv[3]));
        }
    }
}

// ============ Final loss reduce ============
__global__ void reduce_kernel(float* __restrict__ out, int out_size)
{
    if (threadIdx.x != 0 || blockIdx.x != 0) return;
    double a = 0.0, b = 0.0;
    for (int i = 0; i < 8; ++i)   a += g_pc_part[i];
    for (int i = 0; i < 128; ++i) b += g_mse_part[i];
    a /= (double)(B_SZ * D_SZ);
    b /= (double)(B_SZ * R_SZ);
    size_t base = (size_t)B_SZ * S_LEN * D_SZ;
    if ((size_t)out_size >= base + 2) {
        out[base]     = (float)a;
        out[base + 1] = (float)b;
    }
}

extern "C" void kernel_launch(void* const* d_in, const int* in_sizes, int n_in,
                              void* d_out, int out_size)
{
    const float* inputs = (const float*)d_in[0];
    const float* om_in  = (const float*)d_in[1];
    const float* ga_in  = (const float*)d_in[2];
    const float* al_in  = (const float*)d_in[3];
    const float* Wp     = (const float*)d_in[4];
    const float* bp     = (const float*)d_in[5];
    const float* om_r   = (const float*)d_in[6];
    const float* ga_r   = (const float*)d_in[7];
    const float* al_r   = (const float*)d_in[8];
    const float* om_o   = (const float*)d_in[9];
    const float* ga_o   = (const float*)d_in[10];
    const float* al_o   = (const float*)d_in[11];
    const float* Wr     = (const float*)d_in[12];
    const float* brd    = (const float*)d_in[13];
    float* out = (float*)d_out;

    cudaFuncSetAttribute(phaseA_kernel,
        cudaFuncAttributeMaxDynamicSharedMemorySize, 98304);

    dim3 gA(16, 8);
    phaseA_kernel<<<gA, 256, 98304>>>(inputs, om_in, ga_in, al_in, Wp, bp,
                                      om_r, ga_r, al_r, om_o, ga_o, al_o);
    dim3 gB(1024, 2);
    gemm2_kernel<<<gB, 256>>>(Wr, brd, out);
    reduce_kernel<<<1, 1>>>(out, out_size);
}